// round 8
// baseline (speedup 1.0000x reference)
#include <cuda_runtime.h>

// DTCWT 1D forward, 3 levels, fused. Polyphase smem + QUAD-per-thread
// register windows (4 adjacent outputs share one loaded window) =>
// conflict-free, minimal LDS bytes, float4 global stores.
// x: [64,1,2^20] fp32. Outputs: lo3 [64,131072], yh0 [64,524288],
// yh1 [64,2,262144], yh2 [64,2,131072], flattened in that order.

#define T3   256
#define L_IN (1 << 20)
#define L1N  (L_IN / 2)
#define L2N  (L_IN / 4)
#define L3N  (L_IN / 8)

#define XH   1064   // per-phase x tile (2128 floats), xbase = 8*o3-40
#define L1H  530    // per-phase lo1 tile (1060), l1base = 4*o3-18
#define L2H  262    // per-phase lo2 tile (524),  l2base = 2*o3-6

// q-shift filters split into even/odd taps (exact fp32 of reference arrays)
#define DEF_QLO \
    const float f0ae[7] = { 0.00325314f,  0.03466035f, -0.11720389f,  0.75614564f, \
                            0.01186609f,  0.02382538f, -0.00543948f}; \
    const float f0ao[7] = {-0.00388321f, -0.03887280f,  0.27529538f,  0.56881042f, \
                           -0.10671180f,  0.01702522f, -0.00455690f}
#define DEF_QHI \
    const float f1ae[7] = {-0.00455690f,  0.01702522f, -0.10671180f,  0.56881042f, \
                            0.27529538f, -0.03887280f, -0.00388321f}; \
    const float f1ao[7] = { 0.00543948f, -0.02382538f, -0.01186609f, -0.75614564f, \
                            0.11720389f, -0.03466035f, -0.00325314f}; \
    const float f1be[7] = {-0.00325314f, -0.03466035f,  0.11720389f, -0.75614564f, \
                           -0.01186609f, -0.02382538f,  0.00543948f}; \
    const float f1bo[7] = {-0.00388321f, -0.03887280f,  0.27529538f,  0.56881042f, \
                           -0.10671180f,  0.01702522f, -0.00455690f}

__global__ __launch_bounds__(256, 5)
void dtcwt3_quad_kernel(
    const float* __restrict__ x,
    float* __restrict__ out_lo3, float* __restrict__ out_hi1,
    float* __restrict__ out_yh1, float* __restrict__ out_yh2)
{
    __shared__ __align__(8) float sxe[XH], sxo[XH];
    __shared__ __align__(8) float s1e[L1H], s1o[L1H];
    __shared__ __align__(8) float s2e[L2H], s2o[L2H];

    const int tid = threadIdx.x;
    const int row = blockIdx.y;
    const int o3  = blockIdx.x * T3;
    const int xbase = 8 * o3 - 40;
    const float* __restrict__ xr = x + (size_t)row * L_IN;

    // ---- stage x tile (float4), deinterleave into even/odd phases ----
    const bool interior = (xbase >= 0) && (xbase + 2 * XH <= L_IN);
    #pragma unroll
    for (int it = 0; it < 3; it++) {
        int i4 = tid + 256 * it;
        if (i4 < XH / 2) {
            int g = xbase + 4 * i4;
            float4 v;
            if (interior) {
                v = *reinterpret_cast<const float4*>(xr + g);
            } else {
                v.x = ((unsigned)(g    ) < (unsigned)L_IN) ? xr[g    ] : 0.f;
                v.y = ((unsigned)(g + 1) < (unsigned)L_IN) ? xr[g + 1] : 0.f;
                v.z = ((unsigned)(g + 2) < (unsigned)L_IN) ? xr[g + 2] : 0.f;
                v.w = ((unsigned)(g + 3) < (unsigned)L_IN) ? xr[g + 3] : 0.f;
            }
            *reinterpret_cast<float2*>(&sxe[2 * i4]) = make_float2(v.x, v.z);
            *reinterpret_cast<float2*>(&sxo[2 * i4]) = make_float2(v.y, v.w);
        }
    }
    __syncthreads();

    const float2* xe2 = reinterpret_cast<const float2*>(sxe);
    const float2* xo2 = reinterpret_cast<const float2*>(sxo);
    const int l1base = 4 * o3 - 18;

    // ---- level-1 lowpass quads: quad t -> lo1 local [4t..4t+3] ----
    // lo1[idx] = -.05(E[idx+1]+E[idx+3]) + .6 E[idx+2] + .25(O[idx+1]+O[idx+2])
    #pragma unroll
    for (int it = 0; it < 2; it++) {
        int t = tid + 256 * it;
        if (it == 0 || tid < 265 - 256) {
            float2 ea = xe2[2*t], eb = xe2[2*t+1], ec = xe2[2*t+2], ed = xe2[2*t+3];
            float2 oa = xo2[2*t], ob = xo2[2*t+1], oc = xo2[2*t+2];
            float y0 = fmaf(-0.05f, ea.y + eb.y, fmaf(0.6f, eb.x, 0.25f * (oa.y + ob.x)));
            float y1 = fmaf(-0.05f, eb.x + ec.x, fmaf(0.6f, eb.y, 0.25f * (ob.x + ob.y)));
            float y2 = fmaf(-0.05f, eb.y + ec.y, fmaf(0.6f, ec.x, 0.25f * (ob.y + oc.x)));
            float y3 = fmaf(-0.05f, ec.x + ed.x, fmaf(0.6f, ec.y, 0.25f * (oc.x + oc.y)));
            int j0 = l1base + 4 * t;
            if ((unsigned)(j0    ) >= (unsigned)L1N) y0 = 0.f;
            if ((unsigned)(j0 + 1) >= (unsigned)L1N) y1 = 0.f;
            if ((unsigned)(j0 + 2) >= (unsigned)L1N) y2 = 0.f;
            if ((unsigned)(j0 + 3) >= (unsigned)L1N) y3 = 0.f;
            *reinterpret_cast<float2*>(&s1e[2*t]) = make_float2(y0, y2);
            *reinterpret_cast<float2*>(&s1o[2*t]) = make_float2(y1, y3);
        }
    }

    // ---- level-1 highpass quads: quad t -> hi1 local [4t..4t+3] ----
    // hi1[j] = c0(O[j+18]+O[j+21]) + c2(O[j+19]+O[j+20]) + c1(E[j+19]+E[j+21]) + c3 E[j+20]
    {
        const float c0 = -0.0107143f, c1 = 0.0535714f, c2 = 0.2607143f, c3 = -0.6071429f;
        int t = tid;
        float2 o9 = xo2[2*t+9], o10 = xo2[2*t+10], o11 = xo2[2*t+11], o12 = xo2[2*t+12];
        float2 e9 = xe2[2*t+9], e10 = xe2[2*t+10], e11 = xe2[2*t+11], e12v = xe2[2*t+12];
        float4 y;
        y.x = fmaf(c0, o9.x  + o10.y, fmaf(c2, o9.y  + o10.x, fmaf(c1, e9.y  + e10.y, c3 * e10.x)));
        y.y = fmaf(c0, o9.y  + o11.x, fmaf(c2, o10.x + o10.y, fmaf(c1, e10.x + e11.x, c3 * e10.y)));
        y.z = fmaf(c0, o10.x + o11.y, fmaf(c2, o10.y + o11.x, fmaf(c1, e10.y + e11.y, c3 * e11.x)));
        y.w = fmaf(c0, o10.y + o12.x, fmaf(c2, o11.x + o11.y, fmaf(c1, e11.x + e12v.x, c3 * e11.y)));
        *reinterpret_cast<float4*>(out_hi1 + (size_t)row * L1N + 4 * o3 + 4 * t) = y;
    }
    __syncthreads();

    const float2* p1e = reinterpret_cast<const float2*>(s1e);
    const float2* p1o = reinterpret_cast<const float2*>(s1o);

    // ---- level-2, merged: lowpass on tid<131, highpass on tid>=128 ----
    if (tid < 131) {
        DEF_QLO;
        int t = tid;
        float ve[10], vo[10];
        #pragma unroll
        for (int k = 0; k < 5; k++) {
            float2 pe = p1e[2*t + k], po = p1o[2*t + k];
            ve[2*k] = pe.x; ve[2*k+1] = pe.y;
            vo[2*k] = po.x; vo[2*k+1] = po.y;
        }
        float y0 = 0.f, y1 = 0.f, y2 = 0.f, y3 = 0.f;
        #pragma unroll
        for (int k = 0; k < 7; k++) {
            y0 = fmaf(ve[k],   f0ae[k], y0); y0 = fmaf(vo[k],   f0ao[k], y0);
            y1 = fmaf(ve[k+1], f0ae[k], y1); y1 = fmaf(vo[k+1], f0ao[k], y1);
            y2 = fmaf(ve[k+2], f0ae[k], y2); y2 = fmaf(vo[k+2], f0ao[k], y2);
            y3 = fmaf(ve[k+3], f0ae[k], y3); y3 = fmaf(vo[k+3], f0ao[k], y3);
        }
        int g0 = (2 * o3 - 6) + 4 * t;
        if ((unsigned)(g0    ) >= (unsigned)L2N) y0 = 0.f;
        if ((unsigned)(g0 + 1) >= (unsigned)L2N) y1 = 0.f;
        if ((unsigned)(g0 + 2) >= (unsigned)L2N) y2 = 0.f;
        if ((unsigned)(g0 + 3) >= (unsigned)L2N) y3 = 0.f;
        *reinterpret_cast<float2*>(&s2e[2*t]) = make_float2(y0, y2);
        *reinterpret_cast<float2*>(&s2o[2*t]) = make_float2(y1, y3);
    }
    if (tid >= 128) {
        DEF_QHI;
        int t = tid - 128;            // yh1 local quad [4t..4t+3] of 512
        float ve[10], vo[10];
        #pragma unroll
        for (int k = 0; k < 5; k++) {
            float2 pe = p1e[2*t + 3 + k], po = p1o[2*t + 3 + k];
            ve[2*k] = pe.x; ve[2*k+1] = pe.y;
            vo[2*k] = po.x; vo[2*k+1] = po.y;
        }
        float4 a = make_float4(0.f, 0.f, 0.f, 0.f);
        float4 b = make_float4(0.f, 0.f, 0.f, 0.f);
        #pragma unroll
        for (int k = 0; k < 7; k++) {
            float e0 = ve[k], e1 = ve[k+1], e2 = ve[k+2], e3 = ve[k+3];
            float q0 = vo[k], q1 = vo[k+1], q2 = vo[k+2], q3 = vo[k+3];
            a.x = fmaf(e0, f1ae[k], a.x); a.x = fmaf(q0, f1ao[k], a.x);
            a.y = fmaf(e1, f1ae[k], a.y); a.y = fmaf(q1, f1ao[k], a.y);
            a.z = fmaf(e2, f1ae[k], a.z); a.z = fmaf(q2, f1ao[k], a.z);
            a.w = fmaf(e3, f1ae[k], a.w); a.w = fmaf(q3, f1ao[k], a.w);
            b.x = fmaf(e0, f1be[k], b.x); b.x = fmaf(q0, f1bo[k], b.x);
            b.y = fmaf(e1, f1be[k], b.y); b.y = fmaf(q1, f1bo[k], b.y);
            b.z = fmaf(e2, f1be[k], b.z); b.z = fmaf(q2, f1bo[k], b.z);
            b.w = fmaf(e3, f1be[k], b.w); b.w = fmaf(q3, f1bo[k], b.w);
        }
        float* dsta = out_yh1 + (size_t)row * (2 * (size_t)L2N) + 2 * o3;
        *reinterpret_cast<float4*>(dsta + 4 * t)       = a;
        *reinterpret_cast<float4*>(dsta + L2N + 4 * t) = b;
    }
    __syncthreads();

    // ---- level-3 quads: tid < 64, outputs [4t..4t+3] for lo, a, b ----
    if (tid < 64) {
        DEF_QLO; DEF_QHI;
        const float2* p2e = reinterpret_cast<const float2*>(s2e);
        const float2* p2o = reinterpret_cast<const float2*>(s2o);
        int t = tid;
        float ve[10], vo[10];
        #pragma unroll
        for (int k = 0; k < 5; k++) {
            float2 pe = p2e[2*t + k], po = p2o[2*t + k];
            ve[2*k] = pe.x; ve[2*k+1] = pe.y;
            vo[2*k] = po.x; vo[2*k+1] = po.y;
        }
        float4 l = make_float4(0.f, 0.f, 0.f, 0.f);
        float4 a = make_float4(0.f, 0.f, 0.f, 0.f);
        float4 b = make_float4(0.f, 0.f, 0.f, 0.f);
        #pragma unroll
        for (int k = 0; k < 7; k++) {
            float e0 = ve[k], e1 = ve[k+1], e2 = ve[k+2], e3 = ve[k+3];
            float q0 = vo[k], q1 = vo[k+1], q2 = vo[k+2], q3 = vo[k+3];
            l.x = fmaf(e0, f0ae[k], l.x); l.x = fmaf(q0, f0ao[k], l.x);
            l.y = fmaf(e1, f0ae[k], l.y); l.y = fmaf(q1, f0ao[k], l.y);
            l.z = fmaf(e2, f0ae[k], l.z); l.z = fmaf(q2, f0ao[k], l.z);
            l.w = fmaf(e3, f0ae[k], l.w); l.w = fmaf(q3, f0ao[k], l.w);
            a.x = fmaf(e0, f1ae[k], a.x); a.x = fmaf(q0, f1ao[k], a.x);
            a.y = fmaf(e1, f1ae[k], a.y); a.y = fmaf(q1, f1ao[k], a.y);
            a.z = fmaf(e2, f1ae[k], a.z); a.z = fmaf(q2, f1ao[k], a.z);
            a.w = fmaf(e3, f1ae[k], a.w); a.w = fmaf(q3, f1ao[k], a.w);
            b.x = fmaf(e0, f1be[k], b.x); b.x = fmaf(q0, f1bo[k], b.x);
            b.y = fmaf(e1, f1be[k], b.y); b.y = fmaf(q1, f1bo[k], b.y);
            b.z = fmaf(e2, f1be[k], b.z); b.z = fmaf(q2, f1bo[k], b.z);
            b.w = fmaf(e3, f1be[k], b.w); b.w = fmaf(q3, f1bo[k], b.w);
        }
        *reinterpret_cast<float4*>(out_lo3 + (size_t)row * L3N + o3 + 4 * t) = l;
        float* dsta = out_yh2 + (size_t)row * (2 * (size_t)L3N) + o3;
        *reinterpret_cast<float4*>(dsta + 4 * t)       = a;
        *reinterpret_cast<float4*>(dsta + L3N + 4 * t) = b;
    }
}

extern "C" void kernel_launch(void* const* d_in, const int* in_sizes, int n_in,
                              void* d_out, int out_size)
{
    const float* x = (const float*)d_in[0];   // filters folded as immediates

    float* out = (float*)d_out;
    float* out_lo3 = out;                                   // 64 * 131072
    float* out_hi1 = out_lo3 + (size_t)64 * L3N;            // 64 * 524288
    float* out_yh1 = out_hi1 + (size_t)64 * L1N;            // 64 * 2 * 262144
    float* out_yh2 = out_yh1 + (size_t)64 * 2 * L2N;        // 64 * 2 * 131072

    dim3 grid(L3N / T3, 64);
    dtcwt3_quad_kernel<<<grid, 256>>>(x, out_lo3, out_hi1, out_yh1, out_yh2);
}

// round 9
// speedup vs baseline: 1.3699x; 1.3699x over previous
#include <cuda_runtime.h>

// DTCWT 1D forward, 3 levels, fused.
// Level 1 computed straight from a 20-float register window (no smem staging);
// levels 2-3 use conflict-free pair-per-thread polyphase smem with a shared
// window serving both lowpass and highpass at level 2.
// x: [64,1,2^20] fp32. Outputs: lo3 [64,131072], yh0 [64,524288],
// yh1 [64,2,262144], yh2 [64,2,131072], flattened in that order.

#define T3   256
#define L_IN (1 << 20)
#define L1N  (L_IN / 2)
#define L2N  (L_IN / 4)
#define L3N  (L_IN / 8)

#define L1H  530    // per-phase lo1 tile (1060 outputs), l1base = 4*o3-18
#define L2H  262    // per-phase lo2 tile (524 outputs),  l2base = 2*o3-6

// q-shift filters split into even/odd taps (exact fp32 of reference arrays)
#define DEF_QLO \
    const float f0ae[7] = { 0.00325314f,  0.03466035f, -0.11720389f,  0.75614564f, \
                            0.01186609f,  0.02382538f, -0.00543948f}; \
    const float f0ao[7] = {-0.00388321f, -0.03887280f,  0.27529538f,  0.56881042f, \
                           -0.10671180f,  0.01702522f, -0.00455690f}
#define DEF_QHI \
    const float f1ae[7] = {-0.00455690f,  0.01702522f, -0.10671180f,  0.56881042f, \
                            0.27529538f, -0.03887280f, -0.00388321f}; \
    const float f1ao[7] = { 0.00543948f, -0.02382538f, -0.01186609f, -0.75614564f, \
                            0.11720389f, -0.03466035f, -0.00325314f}; \
    const float f1be[7] = {-0.00325314f, -0.03466035f,  0.11720389f, -0.75614564f, \
                           -0.01186609f, -0.02382538f,  0.00543948f}; \
    const float f1bo[7] = {-0.00388321f, -0.03887280f,  0.27529538f,  0.56881042f, \
                           -0.10671180f,  0.01702522f, -0.00455690f}

__global__ __launch_bounds__(256, 5)
void dtcwt3_reg_kernel(
    const float* __restrict__ x,
    float* __restrict__ out_lo3, float* __restrict__ out_hi1,
    float* __restrict__ out_yh1, float* __restrict__ out_yh2)
{
    __shared__ __align__(8) float s1e[L1H], s1o[L1H];
    __shared__ __align__(8) float s2e[L2H], s2o[L2H];

    const int tid = threadIdx.x;
    const int row = blockIdx.y;
    const int o3  = blockIdx.x * T3;
    const float* __restrict__ xr = x + (size_t)row * L_IN;
    const bool boundary = (blockIdx.x == 0) || (blockIdx.x == gridDim.x - 1);

    // ================= LEVEL 1 (register windows, no smem) =================
    {
        // w[k] = x[8*o3 + 8*tid - 4 + k], k = 0..19
        const int gbase = 8 * o3 + 8 * tid - 4;
        float w[20];
        if (!boundary) {
            #pragma unroll
            for (int q = 0; q < 5; q++) {
                float4 v = *reinterpret_cast<const float4*>(xr + gbase + 4 * q);
                w[4*q] = v.x; w[4*q+1] = v.y; w[4*q+2] = v.z; w[4*q+3] = v.w;
            }
        } else {
            #pragma unroll
            for (int k = 0; k < 20; k++) {
                int g = gbase + k;
                w[k] = ((unsigned)g < (unsigned)L_IN) ? xr[g] : 0.f;
            }
        }

        // hi quad tid: outputs i = 4*o3 + 4*tid + r, window w[2r+1 .. 2r+7]
        {
            const float c0 = -0.0107143f, c1 = 0.0535714f,
                        c2 =  0.2607143f, c3 = -0.6071429f;
            float4 y;
            float* yp = &y.x;
            #pragma unroll
            for (int r = 0; r < 4; r++) {
                int b = 2 * r + 1;
                yp[r] = fmaf(c0, w[b] + w[b+6],
                        fmaf(c1, w[b+1] + w[b+5],
                        fmaf(c2, w[b+2] + w[b+4], c3 * w[b+3])));
            }
            *reinterpret_cast<float4*>(out_hi1 + (size_t)row * L1N + 4 * o3 + 4 * tid) = y;
        }

        // lo quad u = tid+5: local idx 4u+r, j = 4*o3+4*tid+2+r, window w[2r+6..2r+10]
        {
            const int u = tid + 5;
            const int j0 = 4 * o3 + 4 * tid + 2;
            float yl[4];
            #pragma unroll
            for (int r = 0; r < 4; r++) {
                int b = 2 * r + 6;
                float v = fmaf(-0.05f, w[b] + w[b+4],
                          fmaf( 0.6f,  w[b+2],
                                0.25f * (w[b+1] + w[b+3])));
                if ((unsigned)(j0 + r) >= (unsigned)L1N) v = 0.f;
                yl[r] = v;
            }
            *reinterpret_cast<float2*>(&s1e[2*u]) = make_float2(yl[0], yl[2]);
            *reinterpret_cast<float2*>(&s1o[2*u]) = make_float2(yl[1], yl[3]);
        }
    }

    // leftover lo quads u' in {0..4} u {261..264} on tids 0..8
    if (tid < 9) {
        const int u = (tid < 5) ? tid : tid + 256;
        const int gb2 = 8 * o3 + 8 * u - 40;   // w2[k] = x[gb2+k], k=0..15
        float w2[16];
        if (!boundary) {
            #pragma unroll
            for (int q = 0; q < 4; q++) {
                float4 v = *reinterpret_cast<const float4*>(xr + gb2 + 4 * q);
                w2[4*q] = v.x; w2[4*q+1] = v.y; w2[4*q+2] = v.z; w2[4*q+3] = v.w;
            }
        } else {
            #pragma unroll
            for (int k = 0; k < 16; k++) {
                int g = gb2 + k;
                w2[k] = ((unsigned)g < (unsigned)L_IN) ? xr[g] : 0.f;
            }
        }
        const int j0 = 4 * o3 - 18 + 4 * u;
        float yl[4];
        #pragma unroll
        for (int r = 0; r < 4; r++) {
            int b = 2 * r + 2;
            float v = fmaf(-0.05f, w2[b] + w2[b+4],
                      fmaf( 0.6f,  w2[b+2],
                            0.25f * (w2[b+1] + w2[b+3])));
            if ((unsigned)(j0 + r) >= (unsigned)L1N) v = 0.f;
            yl[r] = v;
        }
        *reinterpret_cast<float2*>(&s1e[2*u]) = make_float2(yl[0], yl[2]);
        *reinterpret_cast<float2*>(&s1o[2*u]) = make_float2(yl[1], yl[3]);
    }
    __syncthreads();

    // ================= LEVEL 2 (merged lo+hi, shared window) ================
    {
        DEF_QLO; DEF_QHI;
        const float2* p1e = reinterpret_cast<const float2*>(s1e);
        const float2* p1o = reinterpret_cast<const float2*>(s1o);
        float* dsta = out_yh1 + (size_t)row * (2 * (size_t)L2N) + 2 * o3;

        #pragma unroll
        for (int it = 0; it < 2; it++) {
            int t = (it == 0) ? tid : tid + 256;
            if (it == 0 || tid < L2H - 256) {
                float ve[8], vo[8];
                #pragma unroll
                for (int k = 0; k < 4; k++) {
                    float2 pe = p1e[t + k], po = p1o[t + k];
                    ve[2*k] = pe.x; ve[2*k+1] = pe.y;
                    vo[2*k] = po.x; vo[2*k+1] = po.y;
                }
                // lowpass pair (local idx 2t, 2t+1)
                float y0 = 0.f, y1 = 0.f;
                #pragma unroll
                for (int k = 0; k < 7; k++) {
                    y0 = fmaf(ve[k],   f0ae[k], y0); y0 = fmaf(vo[k],   f0ao[k], y0);
                    y1 = fmaf(ve[k+1], f0ae[k], y1); y1 = fmaf(vo[k+1], f0ao[k], y1);
                }
                int g0 = (2 * o3 - 6) + 2 * t;
                if ((unsigned)g0       >= (unsigned)L2N) y0 = 0.f;
                if ((unsigned)(g0 + 1) >= (unsigned)L2N) y1 = 0.f;
                s2e[t] = y0;
                s2o[t] = y1;
                // highpass pair m = t-3 (trees a,b) from the SAME window
                int m = t - 3;
                if ((unsigned)m < 256u) {
                    float a0 = 0.f, a1 = 0.f, b0 = 0.f, b1 = 0.f;
                    #pragma unroll
                    for (int k = 0; k < 7; k++) {
                        float e0 = ve[k], e1 = ve[k+1], q0 = vo[k], q1 = vo[k+1];
                        a0 = fmaf(e0, f1ae[k], a0); a0 = fmaf(q0, f1ao[k], a0);
                        a1 = fmaf(e1, f1ae[k], a1); a1 = fmaf(q1, f1ao[k], a1);
                        b0 = fmaf(e0, f1be[k], b0); b0 = fmaf(q0, f1bo[k], b0);
                        b1 = fmaf(e1, f1be[k], b1); b1 = fmaf(q1, f1bo[k], b1);
                    }
                    reinterpret_cast<float2*>(dsta)[m]       = make_float2(a0, a1);
                    reinterpret_cast<float2*>(dsta + L2N)[m] = make_float2(b0, b1);
                }
            }
        }
    }
    __syncthreads();

    // ================= LEVEL 3 (lo, a, b share one window) ==================
    if (tid < T3 / 2) {
        DEF_QLO; DEF_QHI;
        const float2* p2e = reinterpret_cast<const float2*>(s2e);
        const float2* p2o = reinterpret_cast<const float2*>(s2o);
        int t = tid;
        float ve[8], vo[8];
        #pragma unroll
        for (int k = 0; k < 4; k++) {
            float2 pe = p2e[t + k], po = p2o[t + k];
            ve[2*k] = pe.x; ve[2*k+1] = pe.y;
            vo[2*k] = po.x; vo[2*k+1] = po.y;
        }
        float l0 = 0.f, l1 = 0.f, a0 = 0.f, a1 = 0.f, b0 = 0.f, b1 = 0.f;
        #pragma unroll
        for (int k = 0; k < 7; k++) {
            float e0 = ve[k], e1 = ve[k+1], q0 = vo[k], q1 = vo[k+1];
            l0 = fmaf(e0, f0ae[k], l0); l0 = fmaf(q0, f0ao[k], l0);
            l1 = fmaf(e1, f0ae[k], l1); l1 = fmaf(q1, f0ao[k], l1);
            a0 = fmaf(e0, f1ae[k], a0); a0 = fmaf(q0, f1ao[k], a0);
            a1 = fmaf(e1, f1ae[k], a1); a1 = fmaf(q1, f1ao[k], a1);
            b0 = fmaf(e0, f1be[k], b0); b0 = fmaf(q0, f1bo[k], b0);
            b1 = fmaf(e1, f1be[k], b1); b1 = fmaf(q1, f1bo[k], b1);
        }
        float* dlo  = out_lo3 + (size_t)row * L3N + o3;
        float* dsta = out_yh2 + (size_t)row * (2 * (size_t)L3N) + o3;
        reinterpret_cast<float2*>(dlo )[t]       = make_float2(l0, l1);
        reinterpret_cast<float2*>(dsta)[t]       = make_float2(a0, a1);
        reinterpret_cast<float2*>(dsta + L3N)[t] = make_float2(b0, b1);
    }
}

extern "C" void kernel_launch(void* const* d_in, const int* in_sizes, int n_in,
                              void* d_out, int out_size)
{
    const float* x = (const float*)d_in[0];   // filters folded as immediates

    float* out = (float*)d_out;
    float* out_lo3 = out;                                   // 64 * 131072
    float* out_hi1 = out_lo3 + (size_t)64 * L3N;            // 64 * 524288
    float* out_yh1 = out_hi1 + (size_t)64 * L1N;            // 64 * 2 * 262144
    float* out_yh2 = out_yh1 + (size_t)64 * 2 * L2N;        // 64 * 2 * 131072

    dim3 grid(L3N / T3, 64);
    dtcwt3_reg_kernel<<<grid, 256>>>(x, out_lo3, out_hi1, out_yh1, out_yh2);
}

// round 11
// speedup vs baseline: 1.4425x; 1.0530x over previous
#include <cuda_runtime.h>

// DTCWT 1D forward, 3 levels, fused.
// Level 1: own-data coalesced-ish LDG (2x float4/thread) + warp shuffles to
// assemble the 20-float stencil window (no smem staging, minimal L1 traffic).
// Levels 2-3: conflict-free pair-per-thread polyphase smem, one shared window
// serving lowpass+highpass at level 2 and all three filters at level 3.
// x: [64,1,2^20] fp32. Outputs: lo3 [64,131072], yh0 [64,524288],
// yh1 [64,2,262144], yh2 [64,2,131072], flattened in that order.

#define T3   256
#define L_IN (1 << 20)
#define L1N  (L_IN / 2)
#define L2N  (L_IN / 4)
#define L3N  (L_IN / 8)

#define L1H  530    // per-phase lo1 tile (1060 outputs), l1base = 4*o3-18
#define L2H  262    // per-phase lo2 tile (524 outputs),  l2base = 2*o3-6

// q-shift filters split into even/odd taps (exact fp32 of reference arrays)
#define DEF_QLO \
    const float f0ae[7] = { 0.00325314f,  0.03466035f, -0.11720389f,  0.75614564f, \
                            0.01186609f,  0.02382538f, -0.00543948f}; \
    const float f0ao[7] = {-0.00388321f, -0.03887280f,  0.27529538f,  0.56881042f, \
                           -0.10671180f,  0.01702522f, -0.00455690f}
#define DEF_QHI \
    const float f1ae[7] = {-0.00455690f,  0.01702522f, -0.10671180f,  0.56881042f, \
                            0.27529538f, -0.03887280f, -0.00388321f}; \
    const float f1ao[7] = { 0.00543948f, -0.02382538f, -0.01186609f, -0.75614564f, \
                            0.11720389f, -0.03466035f, -0.00325314f}; \
    const float f1be[7] = {-0.00325314f, -0.03466035f,  0.11720389f, -0.75614564f, \
                           -0.01186609f, -0.02382538f,  0.00543948f}; \
    const float f1bo[7] = {-0.00388321f, -0.03887280f,  0.27529538f,  0.56881042f, \
                           -0.10671180f,  0.01702522f, -0.00455690f}

__device__ __forceinline__ float4 shfl_up4(float4 v) {
    float4 r;
    r.x = __shfl_up_sync(0xFFFFFFFFu, v.x, 1);
    r.y = __shfl_up_sync(0xFFFFFFFFu, v.y, 1);
    r.z = __shfl_up_sync(0xFFFFFFFFu, v.z, 1);
    r.w = __shfl_up_sync(0xFFFFFFFFu, v.w, 1);
    return r;
}
__device__ __forceinline__ float4 shfl_dn4(float4 v) {
    float4 r;
    r.x = __shfl_down_sync(0xFFFFFFFFu, v.x, 1);
    r.y = __shfl_down_sync(0xFFFFFFFFu, v.y, 1);
    r.z = __shfl_down_sync(0xFFFFFFFFu, v.z, 1);
    r.w = __shfl_down_sync(0xFFFFFFFFu, v.w, 1);
    return r;
}

__global__ __launch_bounds__(256, 6)
void dtcwt3_shfl_kernel(
    const float* __restrict__ x,
    float* __restrict__ out_lo3, float* __restrict__ out_hi1,
    float* __restrict__ out_yh1, float* __restrict__ out_yh2)
{
    __shared__ __align__(8) float s1e[L1H], s1o[L1H];
    __shared__ __align__(8) float s2e[L2H], s2o[L2H];

    const int tid  = threadIdx.x;
    const int lane = tid & 31;
    const int row  = blockIdx.y;
    const int o3   = blockIdx.x * T3;
    const float* __restrict__ xr = x + (size_t)row * L_IN;
    const bool boundary = (blockIdx.x == 0) || (blockIdx.x == gridDim.x - 1);

    // ================= LEVEL 1 (shuffle-assembled register windows) ========
    {
        // window w[k] = x[8*o3 + 8*tid - 4 + k], k = 0..19
        float w[20];
        if (!boundary) {
            const int wb = 8 * o3 + 8 * tid;        // own 8 floats: x[wb..wb+7]
            float4 v0 = *reinterpret_cast<const float4*>(xr + wb);
            float4 v1 = *reinterpret_cast<const float4*>(xr + wb + 4);
            float4 up1 = shfl_up4(v1);              // lane-1's v1 = x[wb-4..wb-1]
            float4 dn0 = shfl_dn4(v0);              // x[wb+8..wb+11]
            float4 dn1 = shfl_dn4(v1);              // x[wb+12..wb+15]
            if (lane == 0)
                up1 = *reinterpret_cast<const float4*>(xr + wb - 4);
            if (lane == 31) {
                dn0 = *reinterpret_cast<const float4*>(xr + wb + 8);
                dn1 = *reinterpret_cast<const float4*>(xr + wb + 12);
            }
            w[0]=up1.x; w[1]=up1.y; w[2]=up1.z; w[3]=up1.w;
            w[4]=v0.x;  w[5]=v0.y;  w[6]=v0.z;  w[7]=v0.w;
            w[8]=v1.x;  w[9]=v1.y;  w[10]=v1.z; w[11]=v1.w;
            w[12]=dn0.x; w[13]=dn0.y; w[14]=dn0.z; w[15]=dn0.w;
            w[16]=dn1.x; w[17]=dn1.y; w[18]=dn1.z; w[19]=dn1.w;
        } else {
            const int gbase = 8 * o3 + 8 * tid - 4;
            #pragma unroll
            for (int k = 0; k < 20; k++) {
                int g = gbase + k;
                w[k] = ((unsigned)g < (unsigned)L_IN) ? xr[g] : 0.f;
            }
        }

        // hi quad tid: outputs i = 4*o3 + 4*tid + r, window w[2r+1 .. 2r+7]
        {
            const float c0 = -0.0107143f, c1 = 0.0535714f,
                        c2 =  0.2607143f, c3 = -0.6071429f;
            float4 y;
            float* yp = &y.x;
            #pragma unroll
            for (int r = 0; r < 4; r++) {
                int b = 2 * r + 1;
                yp[r] = fmaf(c0, w[b] + w[b+6],
                        fmaf(c1, w[b+1] + w[b+5],
                        fmaf(c2, w[b+2] + w[b+4], c3 * w[b+3])));
            }
            *reinterpret_cast<float4*>(out_hi1 + (size_t)row * L1N + 4 * o3 + 4 * tid) = y;
        }

        // lo quad u = tid+5: local idx 4u+r, j = 4*o3+4*tid+2+r, window w[2r+6..2r+10]
        {
            const int u = tid + 5;
            const int j0 = 4 * o3 + 4 * tid + 2;
            float yl[4];
            #pragma unroll
            for (int r = 0; r < 4; r++) {
                int b = 2 * r + 6;
                float v = fmaf(-0.05f, w[b] + w[b+4],
                          fmaf( 0.6f,  w[b+2],
                                0.25f * (w[b+1] + w[b+3])));
                if ((unsigned)(j0 + r) >= (unsigned)L1N) v = 0.f;
                yl[r] = v;
            }
            *reinterpret_cast<float2*>(&s1e[2*u]) = make_float2(yl[0], yl[2]);
            *reinterpret_cast<float2*>(&s1o[2*u]) = make_float2(yl[1], yl[3]);
        }
    }

    // leftover lo quads u' in {0..4} u {261..264} on tids 0..8
    if (tid < 9) {
        const int u = (tid < 5) ? tid : tid + 256;
        const int gb2 = 8 * o3 + 8 * u - 40;   // w2[k] = x[gb2+k], k=0..15
        float w2[16];
        if (!boundary) {
            #pragma unroll
            for (int q = 0; q < 4; q++) {
                float4 v = *reinterpret_cast<const float4*>(xr + gb2 + 4 * q);
                w2[4*q] = v.x; w2[4*q+1] = v.y; w2[4*q+2] = v.z; w2[4*q+3] = v.w;
            }
        } else {
            #pragma unroll
            for (int k = 0; k < 16; k++) {
                int g = gb2 + k;
                w2[k] = ((unsigned)g < (unsigned)L_IN) ? xr[g] : 0.f;
            }
        }
        const int j0 = 4 * o3 - 18 + 4 * u;
        float yl[4];
        #pragma unroll
        for (int r = 0; r < 4; r++) {
            int b = 2 * r + 2;
            float v = fmaf(-0.05f, w2[b] + w2[b+4],
                      fmaf( 0.6f,  w2[b+2],
                            0.25f * (w2[b+1] + w2[b+3])));
            if ((unsigned)(j0 + r) >= (unsigned)L1N) v = 0.f;
            yl[r] = v;
        }
        *reinterpret_cast<float2*>(&s1e[2*u]) = make_float2(yl[0], yl[2]);
        *reinterpret_cast<float2*>(&s1o[2*u]) = make_float2(yl[1], yl[3]);
    }
    __syncthreads();

    // ================= LEVEL 2 (merged lo+hi, shared window) ================
    {
        DEF_QLO; DEF_QHI;
        const float2* p1e = reinterpret_cast<const float2*>(s1e);
        const float2* p1o = reinterpret_cast<const float2*>(s1o);
        float* dsta = out_yh1 + (size_t)row * (2 * (size_t)L2N) + 2 * o3;

        #pragma unroll
        for (int it = 0; it < 2; it++) {
            int t = (it == 0) ? tid : tid + 256;
            if (it == 0 || tid < L2H - 256) {
                float ve[8], vo[8];
                #pragma unroll
                for (int k = 0; k < 4; k++) {
                    float2 pe = p1e[t + k], po = p1o[t + k];
                    ve[2*k] = pe.x; ve[2*k+1] = pe.y;
                    vo[2*k] = po.x; vo[2*k+1] = po.y;
                }
                // lowpass pair (local idx 2t, 2t+1)
                float y0 = 0.f, y1 = 0.f;
                #pragma unroll
                for (int k = 0; k < 7; k++) {
                    y0 = fmaf(ve[k],   f0ae[k], y0); y0 = fmaf(vo[k],   f0ao[k], y0);
                    y1 = fmaf(ve[k+1], f0ae[k], y1); y1 = fmaf(vo[k+1], f0ao[k], y1);
                }
                int g0 = (2 * o3 - 6) + 2 * t;
                if ((unsigned)g0       >= (unsigned)L2N) y0 = 0.f;
                if ((unsigned)(g0 + 1) >= (unsigned)L2N) y1 = 0.f;
                s2e[t] = y0;
                s2o[t] = y1;
                // highpass pair m = t-3 (trees a,b) from the SAME window
                int m = t - 3;
                if ((unsigned)m < 256u) {
                    float a0 = 0.f, a1 = 0.f, b0 = 0.f, b1 = 0.f;
                    #pragma unroll
                    for (int k = 0; k < 7; k++) {
                        float e0 = ve[k], e1 = ve[k+1], q0 = vo[k], q1 = vo[k+1];
                        a0 = fmaf(e0, f1ae[k], a0); a0 = fmaf(q0, f1ao[k], a0);
                        a1 = fmaf(e1, f1ae[k], a1); a1 = fmaf(q1, f1ao[k], a1);
                        b0 = fmaf(e0, f1be[k], b0); b0 = fmaf(q0, f1bo[k], b0);
                        b1 = fmaf(e1, f1be[k], b1); b1 = fmaf(q1, f1bo[k], b1);
                    }
                    reinterpret_cast<float2*>(dsta)[m]       = make_float2(a0, a1);
                    reinterpret_cast<float2*>(dsta + L2N)[m] = make_float2(b0, b1);
                }
            }
        }
    }
    __syncthreads();

    // ================= LEVEL 3 (lo, a, b share one window) ==================
    if (tid < T3 / 2) {
        DEF_QLO; DEF_QHI;
        const float2* p2e = reinterpret_cast<const float2*>(s2e);
        const float2* p2o = reinterpret_cast<const float2*>(s2o);
        int t = tid;
        float ve[8], vo[8];
        #pragma unroll
        for (int k = 0; k < 4; k++) {
            float2 pe = p2e[t + k], po = p2o[t + k];
            ve[2*k] = pe.x; ve[2*k+1] = pe.y;
            vo[2*k] = po.x; vo[2*k+1] = po.y;
        }
        float l0 = 0.f, l1 = 0.f, a0 = 0.f, a1 = 0.f, b0 = 0.f, b1 = 0.f;
        #pragma unroll
        for (int k = 0; k < 7; k++) {
            float e0 = ve[k], e1 = ve[k+1], q0 = vo[k], q1 = vo[k+1];
            l0 = fmaf(e0, f0ae[k], l0); l0 = fmaf(q0, f0ao[k], l0);
            l1 = fmaf(e1, f0ae[k], l1); l1 = fmaf(q1, f0ao[k], l1);
            a0 = fmaf(e0, f1ae[k], a0); a0 = fmaf(q0, f1ao[k], a0);
            a1 = fmaf(e1, f1ae[k], a1); a1 = fmaf(q1, f1ao[k], a1);
            b0 = fmaf(e0, f1be[k], b0); b0 = fmaf(q0, f1bo[k], b0);
            b1 = fmaf(e1, f1be[k], b1); b1 = fmaf(q1, f1bo[k], b1);
        }
        float* dlo  = out_lo3 + (size_t)row * L3N + o3;
        float* dsta = out_yh2 + (size_t)row * (2 * (size_t)L3N) + o3;
        reinterpret_cast<float2*>(dlo )[t]       = make_float2(l0, l1);
        reinterpret_cast<float2*>(dsta)[t]       = make_float2(a0, a1);
        reinterpret_cast<float2*>(dsta + L3N)[t] = make_float2(b0, b1);
    }
}

extern "C" void kernel_launch(void* const* d_in, const int* in_sizes, int n_in,
                              void* d_out, int out_size)
{
    const float* x = (const float*)d_in[0];   // filters folded as immediates

    float* out = (float*)d_out;
    float* out_lo3 = out;                                   // 64 * 131072
    float* out_hi1 = out_lo3 + (size_t)64 * L3N;            // 64 * 524288
    float* out_yh1 = out_hi1 + (size_t)64 * L1N;            // 64 * 2 * 262144
    float* out_yh2 = out_yh1 + (size_t)64 * 2 * L2N;        // 64 * 2 * 131072

    dim3 grid(L3N / T3, 64);
    dtcwt3_shfl_kernel<<<grid, 256>>>(x, out_lo3, out_hi1, out_yh1, out_yh2);
}